// round 12
// baseline (speedup 1.0000x reference)
#include <cuda_runtime.h>
#include <cuda_bf16.h>
#include <math.h>
#include <stdint.h>

// ---------------------------------------------------------------------------
// HardNegativeContrastiveLoss N=8192 D=256 T=0.07 top-k=32.
// bf16 mma.sync GEMM + fused top-32/logsumexp.
// R10: explicit register double-buffering of ldmatrix fragments (LDSM for
// k-step u+1 issued before MMAs of step u) to hide shared-memory latency
// behind the tensor pipe; float2-vectorized epilogue scan. Feed path (bulk
// async copies from pre-tiled pre-swizzled gmem, 64 fat steps, 2-buffer B
// ring) unchanged from R9.
// ---------------------------------------------------------------------------

#define N_ROWS 8192
#define DIM    256
#define INV_T  (1.0f / 0.07f)
#define BM     128
#define BN     128
#define NTHREADS 256
#define CHUNK  16384            // 128 rows x 64 bf16 (128B/row), SW128
#define TILE64 65536            // one full 128x256 bf16 tile (4 chunks)
#define NTILE  64
#define OFF_A  0
#define OFF_B  65536
#define DYN_SMEM (1024 + 3 * 65536)   // align slack + A + 2 B buffers
#define STG_LD 66               // staging row stride (floats), anti-conflict

__device__ unsigned char g_img_t[NTILE * TILE64];   // tiled+swizzled bf16
__device__ unsigned char g_cur_t[NTILE * TILE64];
__device__ float g_losses[2 * N_ROWS];

#define SW(o) ((o) ^ (((o) >> 3) & 0x70))

__device__ __forceinline__ uint32_t smem_to_u32(const void* p) {
    uint32_t a;
    asm("{ .reg .u64 t; cvta.to.shared.u64 t, %1; cvt.u32.u64 %0, t; }"
        : "=r"(a) : "l"(p));
    return a;
}
__device__ __forceinline__ void bulk_cp(uint32_t dst, const void* src,
                                        uint32_t bytes, uint32_t mbar) {
    asm volatile(
        "cp.async.bulk.shared::cluster.global.mbarrier::complete_tx::bytes "
        "[%0], [%1], %2, [%3];"
        :: "r"(dst), "l"(src), "r"(bytes), "r"(mbar) : "memory");
}
#define MBARRIER_INIT(mbar, count) \
    asm volatile("mbarrier.init.shared.b64 [%0], %1;" \
        :: "r"((uint32_t)(mbar)), "r"((uint32_t)(count)) : "memory")
#define MBARRIER_EXPECT_TX(mbar, bytes) \
    asm volatile("mbarrier.arrive.expect_tx.shared.b64 _, [%0], %1;" \
        :: "r"((uint32_t)(mbar)), "r"((uint32_t)(bytes)) : "memory")
#define MBARRIER_WAIT_PARITY(mbar, parity) do { \
    uint32_t _m = (uint32_t)(mbar); uint32_t _p = (uint32_t)(parity); uint32_t _d; \
    asm volatile("{\n\t.reg .pred p;\n\t" \
        "mbarrier.try_wait.parity.acquire.cta.shared::cta.b64 p, [%1], %2;\n\t" \
        "selp.b32 %0, 1, 0, p;\n\t}" : "=r"(_d) : "r"(_m), "r"(_p) : "memory"); \
    if (!_d) { \
        asm volatile("{\n\t.reg .pred P1;\n\t" \
            "WL_%=:\n\t" \
            "mbarrier.try_wait.parity.acquire.cta.shared::cta.b64 P1, [%0], %1, 0x989680;\n\t" \
            "@P1 bra.uni WD_%=;\n\t" \
            "bra.uni WL_%=;\n\t" \
            "WD_%=:\n\t}" :: "r"(_m), "r"(_p) : "memory"); \
    } \
} while (0)

__device__ __forceinline__ void ldsm_x4(uint32_t* r, uint32_t addr) {
    asm volatile("ldmatrix.sync.aligned.m8n8.x4.shared.b16 {%0,%1,%2,%3}, [%4];"
                 : "=r"(r[0]), "=r"(r[1]), "=r"(r[2]), "=r"(r[3]) : "r"(addr));
}
__device__ __forceinline__ void mma16816(float* c, const uint32_t* a,
                                         const uint32_t* b) {
    asm volatile(
        "mma.sync.aligned.m16n8k16.row.col.f32.bf16.bf16.f32 "
        "{%0,%1,%2,%3}, {%4,%5,%6,%7}, {%8,%9}, {%0,%1,%2,%3};"
        : "+f"(c[0]), "+f"(c[1]), "+f"(c[2]), "+f"(c[3])
        : "r"(a[0]), "r"(a[1]), "r"(a[2]), "r"(a[3]), "r"(b[0]), "r"(b[1]));
}

// ---------------------------------------------------------------------------
// fp32 -> bf16, written into tiled + SW128-pre-swizzled layout:
// element (n,d) -> tile n/128, chunk d/64, offset SW((n%128)*128 + (d%64)*2)
__global__ void split_kernel(const float* __restrict__ img,
                             const float* __restrict__ cur) {
    int i = blockIdx.x * blockDim.x + threadIdx.x;
    if (i < N_ROWS * DIM) {
        int n = i >> 8, d = i & 255;
        uint32_t off = (uint32_t)(n & 127) * 128u + (uint32_t)(d & 63) * 2u;
        size_t addr = (size_t)(n >> 7) * TILE64 + (size_t)(d >> 6) * CHUNK
                    + SW(off);
        *(__nv_bfloat16*)(g_img_t + addr) = __float2bfloat16(img[i]);
        *(__nv_bfloat16*)(g_cur_t + addr) = __float2bfloat16(cur[i]);
    }
}

// ---------------------------------------------------------------------------
__global__ void __launch_bounds__(NTHREADS, 1)
pass_kernel() {
    extern __shared__ char dsm[];
    __shared__ float stg[128 * STG_LD];      // staging / merge scratch
    __shared__ __align__(8) unsigned long long mbars[2];

    const uint32_t base = (smem_to_u32(dsm) + 1023u) & ~1023u;
    const uint32_t mb0 = smem_to_u32(&mbars[0]);
    const uint32_t mb1 = smem_to_u32(&mbars[1]);
    const int tid    = threadIdx.x;
    const int lane   = tid & 31;
    const int wid    = tid >> 5;
    const int warp_m = wid >> 1;     // 0..3 : rows warp_m*32..+31
    const int warp_n = wid & 1;      // 0..1 : cols warp_n*64..+63
    const int dir    = blockIdx.y;
    const int row0   = blockIdx.x * BM;

    const unsigned char* Xt = dir ? g_cur_t : g_img_t;
    const unsigned char* Yt = dir ? g_img_t : g_cur_t;

    if (tid == 0) { MBARRIER_INIT(mb0, 1); MBARRIER_INIT(mb1, 1); }
    __syncthreads();

    if (tid == 0) {
        // A (64KB) + B tile 0 (64KB) on mb0; B tile 1 on mb1.
        MBARRIER_EXPECT_TX(mb0, TILE64 * 2);
        bulk_cp(base + OFF_A, Xt + (size_t)blockIdx.x * TILE64, TILE64, mb0);
        bulk_cp(base + OFF_B, Yt, TILE64, mb0);
        MBARRIER_EXPECT_TX(mb1, TILE64);
        bulk_cp(base + OFF_B + TILE64, Yt + TILE64, TILE64, mb1);
    }

    // precomputed ldsm relative offsets (within a 16KB chunk, before SW)
    uint32_t b_off[4], a_off[2];
#pragma unroll
    for (int n4 = 0; n4 < 4; n4++)
        b_off[n4] = (uint32_t)(warp_n * 64 + n4 * 16 + ((lane >> 4) & 1) * 8
                  + (lane & 7)) * 128u + (((lane >> 3) & 1) << 4);
#pragma unroll
    for (int mi = 0; mi < 2; mi++)
        a_off[mi] = (uint32_t)(warp_m * 32 + mi * 16 + (lane & 15)) * 128u
                  + ((lane >> 4) << 4);

    // per-thread top-32 (sorted desc, [31]=min) over this thread's half-row
    float list[32];
#pragma unroll
    for (int t = 0; t < 32; t++) list[t] = -INFINITY;
    float pos = -INFINITY;
    const int myrow = tid >> 1;
    const int grow  = row0 + myrow;
    const int chalf = (tid & 1) * 32;

    float acc[2][8][4];
    uint32_t af[2][2][4];        // [pipe][mi][reg]
    uint32_t bf[2][8][2];        // [pipe][nj][reg]

    for (int t = 0; t < NTILE; t++) {
        MBARRIER_WAIT_PARITY(t & 1 ? mb1 : mb0, (t >> 1) & 1);

#pragma unroll
        for (int mi = 0; mi < 2; mi++)
#pragma unroll
            for (int nj = 0; nj < 8; nj++)
#pragma unroll
                for (int e = 0; e < 4; e++) acc[mi][nj][e] = 0.0f;

        const uint32_t bTile = base + OFF_B + (uint32_t)(t & 1) * TILE64;

        // ---- fragment loader for flattened k-step u (kc=u>>2, ks=u&3) ----
#define LOAD_U(u, pb)                                                        \
        do {                                                                 \
            const uint32_t aT_ = base + OFF_A + ((u) >> 2) * CHUNK;          \
            const uint32_t bT_ = bTile + ((u) >> 2) * CHUNK;                 \
            const uint32_t ko_ = ((u) & 3) * 32;                             \
            _Pragma("unroll")                                                \
            for (int n4 = 0; n4 < 4; n4++) {                                 \
                uint32_t off = b_off[n4] + ko_;                              \
                uint32_t r[4];                                               \
                ldsm_x4(r, bT_ + SW(off));                                   \
                bf[pb][2 * n4][0] = r[0]; bf[pb][2 * n4][1] = r[1];          \
                bf[pb][2 * n4 + 1][0] = r[2]; bf[pb][2 * n4 + 1][1] = r[3];  \
            }                                                                \
            _Pragma("unroll")                                                \
            for (int mi = 0; mi < 2; mi++) {                                 \
                uint32_t off = a_off[mi] + ko_;                              \
                ldsm_x4(af[pb][mi], aT_ + SW(off));                          \
            }                                                                \
        } while (0)

        LOAD_U(0, 0);
#pragma unroll
        for (int u = 0; u < 16; u++) {
            if (u < 15) LOAD_U(u + 1, (u + 1) & 1);   // prefetch next k-step
            const int p = u & 1;
#pragma unroll
            for (int mi = 0; mi < 2; mi++)
#pragma unroll
                for (int nj = 0; nj < 8; nj++)
                    mma16816(acc[mi][nj], af[p][mi], bf[p][nj]);
        }
#undef LOAD_U

        // ------- epilogue for tile t: two 64-col halves through stg --------
#pragma unroll
        for (int h = 0; h < 2; h++) {
            __syncthreads();               // h=0: all MMA done -> buffer dead
            if (h == 0 && tid == 0 && t + 2 < NTILE) {
                // refill this step's buffer for step t+2 (reads all done)
                const uint32_t mbr = (t & 1) ? mb1 : mb0;
                MBARRIER_EXPECT_TX(mbr, TILE64);
                bulk_cp(bTile, Yt + (size_t)(t + 2) * TILE64, TILE64, mbr);
            }
            if (warp_n == h) {
#pragma unroll
                for (int mi = 0; mi < 2; mi++)
#pragma unroll
                    for (int nj = 0; nj < 8; nj++) {
                        int r_ = warp_m * 32 + mi * 16 + (lane >> 2);
                        int c_ = nj * 8 + (lane & 3) * 2;
                        *(float2*)&stg[r_ * STG_LD + c_] =
                            make_float2(acc[mi][nj][0], acc[mi][nj][1]);
                        *(float2*)&stg[(r_ + 8) * STG_LD + c_] =
                            make_float2(acc[mi][nj][2], acc[mi][nj][3]);
                    }
            }
            __syncthreads();
            const int cb = t * BN + h * 64 + chalf;
#pragma unroll
            for (int j2 = 0; j2 < 16; j2++) {
                float2 v2 = *(const float2*)&stg[myrow * STG_LD + chalf + j2 * 2];
                float v0 = v2.x * INV_T;
                float v1 = v2.y * INV_T;
                const int dj = grow - (cb + j2 * 2);
                if (dj == 0) { pos = v0; v0 = -INFINITY; }
                if (dj == 1) { pos = v1; v1 = -INFINITY; }
                if (fmaxf(v0, v1) > list[31]) {
                    if (v0 > list[31]) {
                        float x = v0;
#pragma unroll
                        for (int t2 = 0; t2 < 32; t2++) {
                            float a_  = list[t2];
                            float hi_ = fmaxf(a_, x);
                            x         = fminf(a_, x);
                            list[t2]  = hi_;
                        }
                    }
                    if (v1 > list[31]) {
                        float x = v1;
#pragma unroll
                        for (int t2 = 0; t2 < 32; t2++) {
                            float a_  = list[t2];
                            float hi_ = fmaxf(a_, x);
                            x         = fminf(a_, x);
                            list[t2]  = hi_;
                        }
                    }
                }
            }
        }
    }

    // ---- merge the two half-row lists of each row, emit per-row loss ------
    __syncthreads();
    float* fl = stg;                     // 256 slots x 33 floats = 8448 fits
#pragma unroll
    for (int i = 0; i < 32; i++) fl[tid * 33 + i] = list[i];
    fl[tid * 33 + 32] = pos;
    __syncthreads();
    if (!(tid & 1)) {
        const float* A_ = &fl[tid * 33];
        const float* B_ = &fl[(tid + 1) * 33];
        float pm = fmaxf(A_[32], B_[32]);            // the real diagonal logit
        float m  = fmaxf(pm, fmaxf(A_[0], B_[0]));
        float s  = expf(pm - m);
        int ia = 0, ib = 0;
        for (int it = 0; it < 32; it++) {
            float va = (ia < 32) ? A_[ia] : -INFINITY;
            float vb = (ib < 32) ? B_[ib] : -INFINITY;
            if (va >= vb) { s += expf(va - m); ia++; }
            else          { s += expf(vb - m); ib++; }
        }
        g_losses[dir * N_ROWS + grow] = m + logf(s) - pm;
    }
}

// ---------------------------------------------------------------------------
__global__ void reduce_kernel(float* __restrict__ out) {
    __shared__ double red[256];
    double s = 0.0;
    for (int i = threadIdx.x; i < 2 * N_ROWS; i += 256)
        s += (double)g_losses[i];
    red[threadIdx.x] = s;
    __syncthreads();
    for (int off = 128; off > 0; off >>= 1) {
        if (threadIdx.x < off) red[threadIdx.x] += red[threadIdx.x + off];
        __syncthreads();
    }
    if (threadIdx.x == 0)
        out[0] = (float)(red[0] / (double)(2 * N_ROWS));
}

// ---------------------------------------------------------------------------
extern "C" void kernel_launch(void* const* d_in, const int* in_sizes, int n_in,
                              void* d_out, int out_size) {
    const float* img = (const float*)d_in[0];
    const float* cur = (const float*)d_in[1];
    float* out = (float*)d_out;
    (void)in_sizes; (void)n_in; (void)out_size;

    cudaFuncSetAttribute(pass_kernel,
                         cudaFuncAttributeMaxDynamicSharedMemorySize, DYN_SMEM);

    split_kernel<<<(N_ROWS * DIM + 255) / 256, 256>>>(img, cur);
    dim3 grid(NTILE, 2);
    pass_kernel<<<grid, NTHREADS, DYN_SMEM>>>();
    reduce_kernel<<<1, 256>>>(out);
}